// round 10
// baseline (speedup 1.0000x reference)
#include <cuda_runtime.h>
#include <cuda_fp16.h>
#include <math.h>
#include <stdint.h>

#define NB 8
#define NN 2048
#define ND 128
#define BK 64
#define NIT (NN / BK)   // 32 k-chunks
#define ROWB 160u       // gemm smem row stride bytes (80 halves) -> conflict-free LDS.64
#define ZROWB 288u      // k_z smem row stride bytes: 72 mod 32 = 8, conflict-free pattern
#define MT 64           // gemm M-tile rows (64 -> 256 CTAs, 2 CTAs/SM)
#define NTILES (NN / MT)  // 32 tiles per batch
// stage bytes: A MT rows + B 128 rows, 160B each
#define STAGEB ((MT + 128) * 160u)       // 30720
#define ABYTES (MT * 160u)               // 10240

// ---- scratch (__device__ globals: allocation-guard safe) ----
__device__ __half g_dist[(size_t)NB * NN * NN];   // 67 MB, k-pair-permuted, diag has +1
__device__ float  g_dinv[NB * NN];
__device__ __half g_zT[(size_t)NB * ND * NN];     // [b][d][m], permuted in m
__device__ float  g_mean[NB * ND];
__device__ float  g_rstd[NB * ND];
__device__ float2 g_part[NB * NTILES * ND];       // per-(b, n-tile) stats partials

__device__ __forceinline__ uint32_t smem_u32(const void* p) {
    uint32_t a;
    asm("{ .reg .u64 t; cvta.to.shared.u64 t, %1; cvt.u32.u64 %0, t; }" : "=r"(a) : "l"(p));
    return a;
}

// logical k within 16-block -> physical position (pair permutation so that an
// LDS.64 at 4q yields logical pairs {2q,2q+1} and {2q+8,2q+9})
__device__ __forceinline__ int kperm(int w) {
    return 4 * ((w & 7) >> 1) + ((w >> 3) << 1) + (w & 1);
}

// FMA-only sqrt (avoids MUFU throughput wall on 33.5M sqrts)
__device__ __forceinline__ float fast_sqrt(float x) {
    float xh = 0.5f * x;
    float y = __int_as_float(0x5f3759df - (__float_as_int(x) >> 1));
    y = y * (1.5f - xh * y * y);
    y = y * (1.5f - xh * y * y);
    y = y * (1.5f - xh * y * y);
    return x * y;
}

// ---------------------------------------------------------------------------
// Kernel 1: dist rows (fp16, permuted, +1 diag) + degree -> dinv
// ---------------------------------------------------------------------------
__global__ void k_dist(const float* __restrict__ inst) {
    int n = blockIdx.x, b = blockIdx.y;
    const float2* xb = (const float2*)(inst + (size_t)b * NN * 2);
    float2 xn = xb[n];
    float sqn = xn.x * xn.x + xn.y * xn.y;
    __half* drow = g_dist + (size_t)(b * NN + n) * NN;
    float acc = 0.f;
    for (int m = threadIdx.x; m < NN; m += 256) {
        float2 xm = xb[m];
        float sqm = xm.x * xm.x + xm.y * xm.y;
        float dot = xn.x * xm.x + xn.y * xm.y;
        float d2 = sqn + sqm - 2.f * dot;
        float d = (d2 > 0.f) ? fast_sqrt(d2) : 0.f;
        acc += d;
        float v = (m == n) ? d + 1.0f : d;   // fold self-loop into A diagonal
        drow[(m & ~15) + kperm(m & 15)] = __float2half_rn(v);
    }
    __shared__ float red[256];
    red[threadIdx.x] = acc;
    __syncthreads();
    for (int s = 128; s > 0; s >>= 1) {
        if (threadIdx.x < s) red[threadIdx.x] += red[threadIdx.x + s];
        __syncthreads();
    }
    if (threadIdx.x == 0)
        g_dinv[b * NN + n] = rsqrtf(1.0f + red[0]);
}

// ---------------------------------------------------------------------------
// Kernel 2: h0 = instance @ Wn^T + bn
// ---------------------------------------------------------------------------
__global__ void k_proj(const float* __restrict__ inst, const float* __restrict__ Wn,
                       const float* __restrict__ bn, float* __restrict__ h) {
    int idx = blockIdx.x * 256 + threadIdx.x;
    int d = idx & (ND - 1);
    int row = idx >> 7;
    float2 x = ((const float2*)inst)[row];
    h[idx] = x.x * Wn[2 * d] + x.y * Wn[2 * d + 1] + bn[d];
}

// ---------------------------------------------------------------------------
// Kernel 3 (fp16 MMA, output-major): zT[b][e][m] = dinv[m] * sum_d Wg[e,d]*h[m,d]
// ---------------------------------------------------------------------------
__global__ void __launch_bounds__(256) k_z(const float* __restrict__ h,
                                           const float* __restrict__ Wg) {
    extern __shared__ char smc[];
    uint32_t sbase = smem_u32(smc);
    uint32_t as_ = sbase, bs_ = sbase + 128u * ZROWB;   // A=Wg, B=h
    int t = threadIdx.x, l = t & 31, wid = t >> 5;
    int wm = wid & 1, wn = wid >> 1;
    int row0 = blockIdx.x * 128;
    int b = row0 >> 11;
    int m0g = row0 & (NN - 1);

#pragma unroll
    for (int q = 0; q < 16; q++) {
        int idx = q * 256 + t;
        int r = idx >> 5, u = idx & 31;
        float4 wv = *(const float4*)&Wg[r * ND + 4 * u];
        float4 hv = *(const float4*)&h[(size_t)(row0 + r) * ND + 4 * u];
        int blk = u >> 2;
        int p0 = 2 * (u & 3), p1 = p0 + 1;
        int s0 = (p0 < 4) ? 2 * p0 : 2 * (p0 - 4) + 1;
        int s1 = (p1 < 4) ? 2 * p1 : 2 * (p1 - 4) + 1;
        uint32_t base = (uint32_t)(r * ZROWB + blk * 32);
        *(__half2*)(smc + base + s0 * 4) = __floats2half2_rn(wv.x, wv.y);
        *(__half2*)(smc + base + s1 * 4) = __floats2half2_rn(wv.z, wv.w);
        *(__half2*)(smc + 128u * ZROWB + base + s0 * 4) = __floats2half2_rn(hv.x, hv.y);
        *(__half2*)(smc + 128u * ZROWB + base + s1 * 4) = __floats2half2_rn(hv.z, hv.w);
    }
    __syncthreads();

    float c[4][4][4];
#pragma unroll
    for (int i = 0; i < 4; i++)
#pragma unroll
        for (int j = 0; j < 4; j++)
#pragma unroll
            for (int k = 0; k < 4; k++) c[i][j][k] = 0.f;

#pragma unroll
    for (int s = 0; s < 8; s++) {
        uint32_t bf[4][2];
#pragma unroll
        for (int nt = 0; nt < 4; nt++) {
            int nrow = wn * 32 + nt * 8 + (l >> 2);
            asm volatile("ld.shared.v2.b32 {%0,%1}, [%2];"
                         : "=r"(bf[nt][0]), "=r"(bf[nt][1])
                         : "r"(bs_ + (uint32_t)(nrow * ZROWB + s * 32 + (l & 3) * 8)));
        }
#pragma unroll
        for (int mt = 0; mt < 4; mt++) {
            uint32_t af[4];
            int mrow = wm * 64 + mt * 16 + (l >> 2);
            asm volatile("ld.shared.v2.b32 {%0,%1}, [%2];"
                         : "=r"(af[0]), "=r"(af[2])
                         : "r"(as_ + (uint32_t)(mrow * ZROWB + s * 32 + (l & 3) * 8)));
            asm volatile("ld.shared.v2.b32 {%0,%1}, [%2];"
                         : "=r"(af[1]), "=r"(af[3])
                         : "r"(as_ + (uint32_t)((mrow + 8) * ZROWB + s * 32 + (l & 3) * 8)));
#pragma unroll
            for (int nt = 0; nt < 4; nt++) {
                asm volatile(
                    "mma.sync.aligned.m16n8k16.row.col.f32.f16.f16.f32 "
                    "{%0,%1,%2,%3}, {%4,%5,%6,%7}, {%8,%9}, {%0,%1,%2,%3};"
                    : "+f"(c[mt][nt][0]), "+f"(c[mt][nt][1]),
                      "+f"(c[mt][nt][2]), "+f"(c[mt][nt][3])
                    : "r"(af[0]), "r"(af[1]), "r"(af[2]), "r"(af[3]),
                      "r"(bf[nt][0]), "r"(bf[nt][1]));
            }
        }
    }

    float2 dv[4];
#pragma unroll
    for (int nt = 0; nt < 4; nt++)
        dv[nt] = *(const float2*)&g_dinv[b * NN + m0g + wn * 32 + nt * 8 + 2 * (l & 3)];

    __syncthreads();
#pragma unroll
    for (int mt = 0; mt < 4; mt++) {
        int e0 = wm * 64 + mt * 16 + (l >> 2);
#pragma unroll
        for (int nt = 0; nt < 4; nt++) {
            int mloc = wn * 32 + nt * 8 + 2 * (l & 3);
            int phys = (mloc & ~15) + kperm(mloc & 15);
            *(__half2*)(smc + (uint32_t)(e0 * ZROWB + phys * 2)) =
                __floats2half2_rn(c[mt][nt][0] * dv[nt].x, c[mt][nt][1] * dv[nt].y);
            *(__half2*)(smc + (uint32_t)((e0 + 8) * ZROWB + phys * 2)) =
                __floats2half2_rn(c[mt][nt][2] * dv[nt].x, c[mt][nt][3] * dv[nt].y);
        }
    }
    __syncthreads();

    __half* zTb = g_zT + (size_t)b * ND * NN;
#pragma unroll
    for (int it = 0; it < 8; it++) {
        int idx = it * 256 + t;
        int e = idx >> 4, ch = idx & 15;
        uint4 v = *(const uint4*)(smc + (uint32_t)(e * ZROWB + ch * 16));
        *(uint4*)(zTb + (size_t)e * NN + m0g + ch * 8) = v;
    }
}

// ---------------------------------------------------------------------------
// Kernel 4: fp16 m16n8k16 mma.sync GEMM, 64-row M-tiles (2 CTAs/SM) + fused
// stats partials. h[n,:] = tanh( dinv[n]*((dist+I)[n,:] @ z) + bg ) + h[n,:]
// 8 warps = 2 (m) x 4 (n), warp tile 32x32; 3-stage cp.async, BK=64.
// ---------------------------------------------------------------------------
__global__ void __launch_bounds__(256) k_gemm_mma(float* __restrict__ h,
                                                  const float* __restrict__ bg_l) {
    extern __shared__ char smc[];
    uint32_t sbase = smem_u32(smc);
    int t = threadIdx.x, l = t & 31, wid = t >> 5;
    int wm = wid & 1, wn = wid >> 1;
    int b = blockIdx.y, n0 = blockIdx.x * MT;
    const __half* Ab = g_dist + ((size_t)b * NN + n0) * NN;
    const __half* Bt = g_zT + (size_t)b * ND * NN;

    float c[2][4][4];
#pragma unroll
    for (int i = 0; i < 2; i++)
#pragma unroll
        for (int j = 0; j < 4; j++)
#pragma unroll
            for (int k = 0; k < 4; k++) c[i][j][k] = 0.f;

    // stage p: A (MT rows) at p*STAGEB, B (128 rows) at p*STAGEB + ABYTES
#define LOADT(P, K0)                                                             \
    {                                                                            \
        uint32_t xas = sbase + (P) * STAGEB;                                     \
        uint32_t xbs = xas + ABYTES;                                             \
        _Pragma("unroll")                                                        \
        for (int q = 0; q < 2; q++) {          /* A: 512 cp.asyncs */            \
            int idx = q * 256 + t;                                               \
            int r_ = idx >> 3;                                                   \
            int c16 = idx & 7;                                                   \
            asm volatile("cp.async.cg.shared.global [%0], [%1], 16;"             \
                         :: "r"(xas + (uint32_t)(r_ * ROWB + c16 * 16)),         \
                            "l"(Ab + (size_t)r_ * NN + (K0) + c16 * 8));         \
        }                                                                        \
        _Pragma("unroll")                                                        \
        for (int q = 0; q < 4; q++) {          /* B: 1024 cp.asyncs */           \
            int idx = q * 256 + t;                                               \
            int r_ = idx >> 3;                                                   \
            int c16 = idx & 7;                                                   \
            asm volatile("cp.async.cg.shared.global [%0], [%1], 16;"             \
                         :: "r"(xbs + (uint32_t)(r_ * ROWB + c16 * 16)),         \
                            "l"(Bt + (size_t)r_ * NN + (K0) + c16 * 8));         \
        }                                                                        \
        asm volatile("cp.async.commit_group;");                                  \
    }

#define COMPUTE(P)                                                               \
    {                                                                            \
        uint32_t as_ = sbase + (P) * STAGEB;                                     \
        uint32_t bs_ = as_ + ABYTES;                                             \
        _Pragma("unroll")                                                        \
        for (int s = 0; s < 4; s++) {                                            \
            uint32_t bf[4][2];                                                   \
            _Pragma("unroll")                                                    \
            for (int nt = 0; nt < 4; nt++) {                                     \
                int nrow = wn * 32 + nt * 8 + (l >> 2);                          \
                asm volatile("ld.shared.v2.b32 {%0,%1}, [%2];"                   \
                             : "=r"(bf[nt][0]), "=r"(bf[nt][1])                  \
                             : "r"(bs_ + (uint32_t)(nrow * ROWB + s * 32 + (l & 3) * 8))); \
            }                                                                    \
            _Pragma("unroll")                                                    \
            for (int mt = 0; mt < 2; mt++) {                                     \
                uint32_t af[4];                                                  \
                int mrow = wm * 32 + mt * 16 + (l >> 2);                         \
                asm volatile("ld.shared.v2.b32 {%0,%1}, [%2];"                   \
                             : "=r"(af[0]), "=r"(af[2])                          \
                             : "r"(as_ + (uint32_t)(mrow * ROWB + s * 32 + (l & 3) * 8))); \
                asm volatile("ld.shared.v2.b32 {%0,%1}, [%2];"                   \
                             : "=r"(af[1]), "=r"(af[3])                          \
                             : "r"(as_ + (uint32_t)((mrow + 8) * ROWB + s * 32 + (l & 3) * 8))); \
                _Pragma("unroll")                                                \
                for (int nt = 0; nt < 4; nt++) {                                 \
                    asm volatile(                                                \
                        "mma.sync.aligned.m16n8k16.row.col.f32.f16.f16.f32 "     \
                        "{%0,%1,%2,%3}, {%4,%5,%6,%7}, {%8,%9}, {%0,%1,%2,%3};"  \
                        : "+f"(c[mt][nt][0]), "+f"(c[mt][nt][1]),                \
                          "+f"(c[mt][nt][2]), "+f"(c[mt][nt][3])                 \
                        : "r"(af[0]), "r"(af[1]), "r"(af[2]), "r"(af[3]),        \
                          "r"(bf[nt][0]), "r"(bf[nt][1]));                       \
                }                                                                \
            }                                                                    \
        }                                                                        \
    }

    LOADT(0, 0);
    LOADT(1, BK);
    int p = 0;
    for (int it = 0; it < NIT; it++) {
        if (it + 1 < NIT)
            asm volatile("cp.async.wait_group 1;");
        else
            asm volatile("cp.async.wait_group 0;");
        __syncthreads();
        if (it + 2 < NIT) {
            int pn = (it + 2) % 3;
            LOADT(pn, (it + 2) * BK);
        }
        COMPUTE(p);
        p = (p + 1) % 3;
    }

    // epilogue: dinv + bias + tanh + residual, accumulating stats partials
    float ssum[8], ssq[8];
#pragma unroll
    for (int j = 0; j < 8; j++) { ssum[j] = 0.f; ssq[j] = 0.f; }
#pragma unroll
    for (int mt = 0; mt < 2; mt++) {
        int r0 = n0 + wm * 32 + mt * 16 + (l >> 2);
        int r1 = r0 + 8;
        float dv0 = g_dinv[b * NN + r0];
        float dv1 = g_dinv[b * NN + r1];
#pragma unroll
        for (int nt = 0; nt < 4; nt++) {
            int cc = wn * 32 + nt * 8 + 2 * (l & 3);
            float bg0 = bg_l[cc], bg1 = bg_l[cc + 1];
            size_t h0o = ((size_t)b * NN + r0) * ND + cc;
            size_t h1o = ((size_t)b * NN + r1) * ND + cc;
            float2 hv0 = *(const float2*)&h[h0o];
            float2 hv1 = *(const float2*)&h[h1o];
            float2 o0, o1;
            o0.x = tanhf(dv0 * c[mt][nt][0] + bg0) + hv0.x;
            o0.y = tanhf(dv0 * c[mt][nt][1] + bg1) + hv0.y;
            o1.x = tanhf(dv1 * c[mt][nt][2] + bg0) + hv1.x;
            o1.y = tanhf(dv1 * c[mt][nt][3] + bg1) + hv1.y;
            *(float2*)&h[h0o] = o0;
            *(float2*)&h[h1o] = o1;
            ssum[2 * nt]     += o0.x + o1.x;
            ssum[2 * nt + 1] += o0.y + o1.y;
            ssq[2 * nt]      += o0.x * o0.x + o1.x * o1.x;
            ssq[2 * nt + 1]  += o0.y * o0.y + o1.y * o1.y;
        }
    }
#pragma unroll
    for (int off = 4; off < 32; off <<= 1)
#pragma unroll
        for (int j = 0; j < 8; j++) {
            ssum[j] += __shfl_xor_sync(0xffffffffu, ssum[j], off);
            ssq[j]  += __shfl_xor_sync(0xffffffffu, ssq[j], off);
        }
    __syncthreads();           // mainloop smem dead; reuse for cross-warp stats
    float* sp = (float*)smc;   // [0:256) sums (wm-major), [256:512) sumsqs
    if ((l >> 2) == 0) {
#pragma unroll
        for (int j = 0; j < 8; j++) {
            int col = wn * 32 + (j >> 1) * 8 + 2 * (l & 3) + (j & 1);
            sp[wm * 128 + col] = ssum[j];
            sp[256 + wm * 128 + col] = ssq[j];
        }
    }
    __syncthreads();
    if (t < 128) {
        float s = sp[t] + sp[128 + t];
        float q = sp[256 + t] + sp[384 + t];
        g_part[((size_t)b * NTILES + blockIdx.x) * ND + t] = make_float2(s, q);
    }
#undef LOADT
#undef COMPUTE
}

// ---------------------------------------------------------------------------
// Kernel 5: finalize GraphNorm stats from NTILES per-tile partials
// ---------------------------------------------------------------------------
__global__ void k_fin(const float* __restrict__ gna) {
    int b = blockIdx.x, d = threadIdx.x;
    float s = 0.f, q = 0.f;
#pragma unroll
    for (int tile = 0; tile < NTILES; tile++) {
        float2 v = g_part[((size_t)b * NTILES + tile) * ND + d];
        s += v.x; q += v.y;
    }
    float mean = s * (1.f / NN);
    float eh2 = q * (1.f / NN);
    float a = gna[d];
    float var = eh2 - (2.f * a - a * a) * mean * mean;
    g_mean[b * ND + d] = mean;
    g_rstd[b * ND + d] = rsqrtf(var + 1e-5f);
}

// ---------------------------------------------------------------------------
// Kernel 6: normalize in place
// ---------------------------------------------------------------------------
__global__ void k_norm(float* __restrict__ h, const float* __restrict__ gnw,
                       const float* __restrict__ gnb, const float* __restrict__ gna) {
    int idx = blockIdx.x * 256 + threadIdx.x;
    int d = idx & (ND - 1);
    int b = idx >> 18;
    float m = g_mean[b * ND + d];
    float rs = g_rstd[b * ND + d];
    float v = h[idx];
    h[idx] = gnw[d] * (v - gna[d] * m) * rs + gnb[d];
}

// ---------------------------------------------------------------------------
extern "C" void kernel_launch(void* const* d_in, const int* in_sizes, int n_in,
                              void* d_out, int out_size) {
    const float* inst = (const float*)d_in[0];
    const float* Wn   = (const float*)d_in[1];
    const float* bn   = (const float*)d_in[2];
    const float* Wg   = (const float*)d_in[3];
    const float* bg   = (const float*)d_in[4];
    const float* gnw  = (const float*)d_in[5];
    const float* gnb  = (const float*)d_in[6];
    const float* gna  = (const float*)d_in[7];
    float* h = (float*)d_out;

    const int SMEM_GEMM = 3 * (int)STAGEB;       // 92160 B -> 2 CTAs/SM
    const int SMEM_Z    = 2 * 128 * (int)ZROWB;  // 72 KB
    static int smem_set = 0;
    if (!smem_set) {
        cudaFuncSetAttribute(k_gemm_mma, cudaFuncAttributeMaxDynamicSharedMemorySize, SMEM_GEMM);
        cudaFuncSetAttribute(k_z, cudaFuncAttributeMaxDynamicSharedMemorySize, SMEM_Z);
        smem_set = 1;
    }

    k_dist<<<dim3(NN, NB), 256>>>(inst);
    k_proj<<<(NB * NN * ND) / 256, 256>>>(inst, Wn, bn, h);
    for (int l = 0; l < 3; l++) {
        k_z<<<NB * NN / 128, 256, SMEM_Z>>>(h, Wg + l * ND * ND);
        k_gemm_mma<<<dim3(NTILES, NB), 256, SMEM_GEMM>>>(h, bg + l * ND);
        k_fin<<<NB, ND>>>(gna);
        k_norm<<<(NB * NN * ND) / 256, 256>>>(h, gnw, gnb, gna);
    }
}

// round 11
// speedup vs baseline: 1.0350x; 1.0350x over previous
#include <cuda_runtime.h>
#include <cuda_fp16.h>
#include <math.h>
#include <stdint.h>

#define NB 8
#define NN 2048
#define ND 128
#define BK 64
#define NIT (NN / BK)   // 32 k-chunks
#define ROWB 160u       // gemm smem row stride bytes (80 halves) -> conflict-free LDS.64
#define ZROWB 288u      // k_z smem row stride bytes: 72 mod 32 = 8, conflict-free pattern
#define NTILES 16       // gemm M-tiles per batch (128 rows each)

// ---- scratch (__device__ globals: allocation-guard safe) ----
__device__ __half g_dist[(size_t)NB * NN * NN];   // 67 MB, k-pair-permuted, diag has +1
__device__ float  g_dinv[NB * NN];
__device__ __half g_zT[(size_t)NB * ND * NN];     // [b][d][m], permuted in m
__device__ float  g_mean[NB * ND];
__device__ float  g_rstd[NB * ND];
__device__ float2 g_part[NB * NTILES * ND];       // per-(b, n-tile) stats partials

__device__ __forceinline__ uint32_t smem_u32(const void* p) {
    uint32_t a;
    asm("{ .reg .u64 t; cvta.to.shared.u64 t, %1; cvt.u32.u64 %0, t; }" : "=r"(a) : "l"(p));
    return a;
}

// logical k within 16-block -> physical position (pair permutation so that an
// LDS.64 at 4q yields logical pairs {2q,2q+1} and {2q+8,2q+9})
__device__ __forceinline__ int kperm(int w) {
    return 4 * ((w & 7) >> 1) + ((w >> 3) << 1) + (w & 1);
}

// FMA-only sqrt (avoids MUFU throughput wall on 33.5M sqrts)
__device__ __forceinline__ float fast_sqrt(float x) {
    float xh = 0.5f * x;
    float y = __int_as_float(0x5f3759df - (__float_as_int(x) >> 1));
    y = y * (1.5f - xh * y * y);
    y = y * (1.5f - xh * y * y);
    y = y * (1.5f - xh * y * y);
    return x * y;
}

// ---------------------------------------------------------------------------
// Kernel 1: dist rows (fp16, permuted, +1 diag) + degree -> dinv
// ---------------------------------------------------------------------------
__global__ void k_dist(const float* __restrict__ inst) {
    int n = blockIdx.x, b = blockIdx.y;
    const float2* xb = (const float2*)(inst + (size_t)b * NN * 2);
    float2 xn = xb[n];
    float sqn = xn.x * xn.x + xn.y * xn.y;
    __half* drow = g_dist + (size_t)(b * NN + n) * NN;
    float acc = 0.f;
    for (int m = threadIdx.x; m < NN; m += 256) {
        float2 xm = xb[m];
        float sqm = xm.x * xm.x + xm.y * xm.y;
        float dot = xn.x * xm.x + xn.y * xm.y;
        float d2 = sqn + sqm - 2.f * dot;
        float d = (d2 > 0.f) ? fast_sqrt(d2) : 0.f;
        acc += d;
        float v = (m == n) ? d + 1.0f : d;   // fold self-loop into A diagonal
        drow[(m & ~15) + kperm(m & 15)] = __float2half_rn(v);
    }
    __shared__ float red[256];
    red[threadIdx.x] = acc;
    __syncthreads();
    for (int s = 128; s > 0; s >>= 1) {
        if (threadIdx.x < s) red[threadIdx.x] += red[threadIdx.x + s];
        __syncthreads();
    }
    if (threadIdx.x == 0)
        g_dinv[b * NN + n] = rsqrtf(1.0f + red[0]);
}

// ---------------------------------------------------------------------------
// Kernel 2: h0 = instance @ Wn^T + bn
// ---------------------------------------------------------------------------
__global__ void k_proj(const float* __restrict__ inst, const float* __restrict__ Wn,
                       const float* __restrict__ bn, float* __restrict__ h) {
    int idx = blockIdx.x * 256 + threadIdx.x;
    int d = idx & (ND - 1);
    int row = idx >> 7;
    float2 x = ((const float2*)inst)[row];
    h[idx] = x.x * Wn[2 * d] + x.y * Wn[2 * d + 1] + bn[d];
}

// ---------------------------------------------------------------------------
// Kernel 3 (fp16 MMA, output-major): zT[b][e][m] = dinv[m] * sum_d Wg[e,d]*h[m,d]
// Optionally fuses the PREVIOUS layer's GraphNorm: normalizes h during staging
// and writes normalized h back to global (gemm's residual read sees it).
// ---------------------------------------------------------------------------
__global__ void __launch_bounds__(256) k_z(float* __restrict__ h,
                                           const float* __restrict__ Wg,
                                           int do_norm,
                                           const float* __restrict__ gnw,
                                           const float* __restrict__ gnb,
                                           const float* __restrict__ gna) {
    extern __shared__ char smc[];
    uint32_t sbase = smem_u32(smc);
    uint32_t as_ = sbase, bs_ = sbase + 128u * ZROWB;   // A=Wg, B=h
    int t = threadIdx.x, l = t & 31, wid = t >> 5;
    int wm = wid & 1, wn = wid >> 1;
    int row0 = blockIdx.x * 128;
    int b = row0 >> 11;
    int m0g = row0 & (NN - 1);

#pragma unroll
    for (int q = 0; q < 16; q++) {
        int idx = q * 256 + t;
        int r = idx >> 5, u = idx & 31;
        float4 wv = *(const float4*)&Wg[r * ND + 4 * u];
        float4 hv = *(const float4*)&h[(size_t)(row0 + r) * ND + 4 * u];
        if (do_norm) {
            float4 mw = *(const float4*)&g_mean[b * ND + 4 * u];
            float4 rw = *(const float4*)&g_rstd[b * ND + 4 * u];
            float4 w_ = *(const float4*)&gnw[4 * u];
            float4 b_ = *(const float4*)&gnb[4 * u];
            float4 a_ = *(const float4*)&gna[4 * u];
            hv.x = w_.x * (hv.x - a_.x * mw.x) * rw.x + b_.x;
            hv.y = w_.y * (hv.y - a_.y * mw.y) * rw.y + b_.y;
            hv.z = w_.z * (hv.z - a_.z * mw.z) * rw.z + b_.z;
            hv.w = w_.w * (hv.w - a_.w * mw.w) * rw.w + b_.w;
            *(float4*)&h[(size_t)(row0 + r) * ND + 4 * u] = hv;
        }
        int blk = u >> 2;
        int p0 = 2 * (u & 3), p1 = p0 + 1;
        int s0 = (p0 < 4) ? 2 * p0 : 2 * (p0 - 4) + 1;
        int s1 = (p1 < 4) ? 2 * p1 : 2 * (p1 - 4) + 1;
        uint32_t base = (uint32_t)(r * ZROWB + blk * 32);
        *(__half2*)(smc + base + s0 * 4) = __floats2half2_rn(wv.x, wv.y);
        *(__half2*)(smc + base + s1 * 4) = __floats2half2_rn(wv.z, wv.w);
        *(__half2*)(smc + 128u * ZROWB + base + s0 * 4) = __floats2half2_rn(hv.x, hv.y);
        *(__half2*)(smc + 128u * ZROWB + base + s1 * 4) = __floats2half2_rn(hv.z, hv.w);
    }
    __syncthreads();

    float c[4][4][4];
#pragma unroll
    for (int i = 0; i < 4; i++)
#pragma unroll
        for (int j = 0; j < 4; j++)
#pragma unroll
            for (int k = 0; k < 4; k++) c[i][j][k] = 0.f;

#pragma unroll
    for (int s = 0; s < 8; s++) {
        uint32_t bf[4][2];
#pragma unroll
        for (int nt = 0; nt < 4; nt++) {
            int nrow = wn * 32 + nt * 8 + (l >> 2);
            asm volatile("ld.shared.v2.b32 {%0,%1}, [%2];"
                         : "=r"(bf[nt][0]), "=r"(bf[nt][1])
                         : "r"(bs_ + (uint32_t)(nrow * ZROWB + s * 32 + (l & 3) * 8)));
        }
#pragma unroll
        for (int mt = 0; mt < 4; mt++) {
            uint32_t af[4];
            int mrow = wm * 64 + mt * 16 + (l >> 2);
            asm volatile("ld.shared.v2.b32 {%0,%1}, [%2];"
                         : "=r"(af[0]), "=r"(af[2])
                         : "r"(as_ + (uint32_t)(mrow * ZROWB + s * 32 + (l & 3) * 8)));
            asm volatile("ld.shared.v2.b32 {%0,%1}, [%2];"
                         : "=r"(af[1]), "=r"(af[3])
                         : "r"(as_ + (uint32_t)((mrow + 8) * ZROWB + s * 32 + (l & 3) * 8)));
#pragma unroll
            for (int nt = 0; nt < 4; nt++) {
                asm volatile(
                    "mma.sync.aligned.m16n8k16.row.col.f32.f16.f16.f32 "
                    "{%0,%1,%2,%3}, {%4,%5,%6,%7}, {%8,%9}, {%0,%1,%2,%3};"
                    : "+f"(c[mt][nt][0]), "+f"(c[mt][nt][1]),
                      "+f"(c[mt][nt][2]), "+f"(c[mt][nt][3])
                    : "r"(af[0]), "r"(af[1]), "r"(af[2]), "r"(af[3]),
                      "r"(bf[nt][0]), "r"(bf[nt][1]));
            }
        }
    }

    float2 dv[4];
#pragma unroll
    for (int nt = 0; nt < 4; nt++)
        dv[nt] = *(const float2*)&g_dinv[b * NN + m0g + wn * 32 + nt * 8 + 2 * (l & 3)];

    __syncthreads();
#pragma unroll
    for (int mt = 0; mt < 4; mt++) {
        int e0 = wm * 64 + mt * 16 + (l >> 2);
#pragma unroll
        for (int nt = 0; nt < 4; nt++) {
            int mloc = wn * 32 + nt * 8 + 2 * (l & 3);
            int phys = (mloc & ~15) + kperm(mloc & 15);
            *(__half2*)(smc + (uint32_t)(e0 * ZROWB + phys * 2)) =
                __floats2half2_rn(c[mt][nt][0] * dv[nt].x, c[mt][nt][1] * dv[nt].y);
            *(__half2*)(smc + (uint32_t)((e0 + 8) * ZROWB + phys * 2)) =
                __floats2half2_rn(c[mt][nt][2] * dv[nt].x, c[mt][nt][3] * dv[nt].y);
        }
    }
    __syncthreads();

    __half* zTb = g_zT + (size_t)b * ND * NN;
#pragma unroll
    for (int it = 0; it < 8; it++) {
        int idx = it * 256 + t;
        int e = idx >> 4, ch = idx & 15;
        uint4 v = *(const uint4*)(smc + (uint32_t)(e * ZROWB + ch * 16));
        *(uint4*)(zTb + (size_t)e * NN + m0g + ch * 8) = v;
    }
}

// ---------------------------------------------------------------------------
// Kernel 4: fp16 m16n8k16 mma.sync GEMM, MT=128, 512 threads (16 warps 4x4,
// warp tile 32x32) + fused stats partials.
// h[n,:] = tanh( dinv[n]*((dist+I)[n,:] @ z) + bg ) + h[n,:]
// ---------------------------------------------------------------------------
__global__ void __launch_bounds__(512) k_gemm_mma(float* __restrict__ h,
                                                  const float* __restrict__ bg_l) {
    extern __shared__ char smc[];
    uint32_t sbase = smem_u32(smc);
    int t = threadIdx.x, l = t & 31, wid = t >> 5;
    int wm = wid & 3, wn = wid >> 2;     // 4 x 4 warp grid
    int b = blockIdx.y, n0 = blockIdx.x * 128;
    const __half* Ab = g_dist + ((size_t)b * NN + n0) * NN;
    const __half* Bt = g_zT + (size_t)b * ND * NN;

    float c[2][4][4];
#pragma unroll
    for (int i = 0; i < 2; i++)
#pragma unroll
        for (int j = 0; j < 4; j++)
#pragma unroll
            for (int k = 0; k < 4; k++) c[i][j][k] = 0.f;

#define LOADT(P, K0)                                                             \
    {                                                                            \
        uint32_t xas = sbase + (P) * 40960u;                                     \
        uint32_t xbs = xas + 20480u;                                             \
        _Pragma("unroll")                                                        \
        for (int q = 0; q < 2; q++) {                                            \
            int idx = q * 512 + t;                                               \
            int r_ = idx >> 3;                                                   \
            int c16 = idx & 7;                                                   \
            uint32_t so = (uint32_t)(r_ * ROWB + c16 * 16);                      \
            asm volatile("cp.async.cg.shared.global [%0], [%1], 16;"             \
                         :: "r"(xas + so), "l"(Ab + (size_t)r_ * NN + (K0) + c16 * 8)); \
            asm volatile("cp.async.cg.shared.global [%0], [%1], 16;"             \
                         :: "r"(xbs + so), "l"(Bt + (size_t)r_ * NN + (K0) + c16 * 8)); \
        }                                                                        \
        asm volatile("cp.async.commit_group;");                                  \
    }

#define COMPUTE(P)                                                               \
    {                                                                            \
        uint32_t as_ = sbase + (P) * 40960u;                                     \
        uint32_t bs_ = as_ + 20480u;                                             \
        _Pragma("unroll")                                                        \
        for (int s = 0; s < 4; s++) {                                            \
            uint32_t bf[4][2];                                                   \
            _Pragma("unroll")                                                    \
            for (int nt = 0; nt < 4; nt++) {                                     \
                int nrow = wn * 32 + nt * 8 + (l >> 2);                          \
                asm volatile("ld.shared.v2.b32 {%0,%1}, [%2];"                   \
                             : "=r"(bf[nt][0]), "=r"(bf[nt][1])                  \
                             : "r"(bs_ + (uint32_t)(nrow * ROWB + s * 32 + (l & 3) * 8))); \
            }                                                                    \
            _Pragma("unroll")                                                    \
            for (int mt = 0; mt < 2; mt++) {                                     \
                uint32_t af[4];                                                  \
                int mrow = wm * 32 + mt * 16 + (l >> 2);                         \
                asm volatile("ld.shared.v2.b32 {%0,%1}, [%2];"                   \
                             : "=r"(af[0]), "=r"(af[2])                          \
                             : "r"(as_ + (uint32_t)(mrow * ROWB + s * 32 + (l & 3) * 8))); \
                asm volatile("ld.shared.v2.b32 {%0,%1}, [%2];"                   \
                             : "=r"(af[1]), "=r"(af[3])                          \
                             : "r"(as_ + (uint32_t)((mrow + 8) * ROWB + s * 32 + (l & 3) * 8))); \
                _Pragma("unroll")                                                \
                for (int nt = 0; nt < 4; nt++) {                                 \
                    asm volatile(                                                \
                        "mma.sync.aligned.m16n8k16.row.col.f32.f16.f16.f32 "     \
                        "{%0,%1,%2,%3}, {%4,%5,%6,%7}, {%8,%9}, {%0,%1,%2,%3};"  \
                        : "+f"(c[mt][nt][0]), "+f"(c[mt][nt][1]),                \
                          "+f"(c[mt][nt][2]), "+f"(c[mt][nt][3])                 \
                        : "r"(af[0]), "r"(af[1]), "r"(af[2]), "r"(af[3]),        \
                          "r"(bf[nt][0]), "r"(bf[nt][1]));                       \
                }                                                                \
            }                                                                    \
        }                                                                        \
    }

    LOADT(0, 0);
    LOADT(1, BK);
    int p = 0;
    for (int it = 0; it < NIT; it++) {
        if (it + 1 < NIT)
            asm volatile("cp.async.wait_group 1;");
        else
            asm volatile("cp.async.wait_group 0;");
        __syncthreads();
        if (it + 2 < NIT) {
            int pn = (it + 2) % 3;
            LOADT(pn, (it + 2) * BK);
        }
        COMPUTE(p);
        p = (p + 1) % 3;
    }

    // epilogue: dinv + bias + tanh + residual, accumulating stats partials
    float ssum[8], ssq[8];
#pragma unroll
    for (int j = 0; j < 8; j++) { ssum[j] = 0.f; ssq[j] = 0.f; }
#pragma unroll
    for (int mt = 0; mt < 2; mt++) {
        int r0 = n0 + wm * 32 + mt * 16 + (l >> 2);
        int r1 = r0 + 8;
        float dv0 = g_dinv[b * NN + r0];
        float dv1 = g_dinv[b * NN + r1];
#pragma unroll
        for (int nt = 0; nt < 4; nt++) {
            int cc = wn * 32 + nt * 8 + 2 * (l & 3);
            float bg0 = bg_l[cc], bg1 = bg_l[cc + 1];
            size_t h0o = ((size_t)b * NN + r0) * ND + cc;
            size_t h1o = ((size_t)b * NN + r1) * ND + cc;
            float2 hv0 = *(const float2*)&h[h0o];
            float2 hv1 = *(const float2*)&h[h1o];
            float2 o0, o1;
            o0.x = tanhf(dv0 * c[mt][nt][0] + bg0) + hv0.x;
            o0.y = tanhf(dv0 * c[mt][nt][1] + bg1) + hv0.y;
            o1.x = tanhf(dv1 * c[mt][nt][2] + bg0) + hv1.x;
            o1.y = tanhf(dv1 * c[mt][nt][3] + bg1) + hv1.y;
            *(float2*)&h[h0o] = o0;
            *(float2*)&h[h1o] = o1;
            ssum[2 * nt]     += o0.x + o1.x;
            ssum[2 * nt + 1] += o0.y + o1.y;
            ssq[2 * nt]      += o0.x * o0.x + o1.x * o1.x;
            ssq[2 * nt + 1]  += o0.y * o0.y + o1.y * o1.y;
        }
    }
#pragma unroll
    for (int off = 4; off < 32; off <<= 1)
#pragma unroll
        for (int j = 0; j < 8; j++) {
            ssum[j] += __shfl_xor_sync(0xffffffffu, ssum[j], off);
            ssq[j]  += __shfl_xor_sync(0xffffffffu, ssq[j], off);
        }
    __syncthreads();           // mainloop smem dead; reuse for cross-warp stats
    float* sp = (float*)smc;   // [0:512) sums (wm-major), [512:1024) sumsqs
    if ((l >> 2) == 0) {
#pragma unroll
        for (int j = 0; j < 8; j++) {
            int col = wn * 32 + (j >> 1) * 8 + 2 * (l & 3) + (j & 1);
            sp[wm * 128 + col] = ssum[j];
            sp[512 + wm * 128 + col] = ssq[j];
        }
    }
    __syncthreads();
    if (t < 128) {
        float s = sp[t] + sp[128 + t] + sp[256 + t] + sp[384 + t];
        float q = sp[512 + t] + sp[640 + t] + sp[768 + t] + sp[896 + t];
        g_part[((size_t)b * NTILES + blockIdx.x) * ND + t] = make_float2(s, q);
    }
#undef LOADT
#undef COMPUTE
}

// ---------------------------------------------------------------------------
// Kernel 5: finalize GraphNorm stats from NTILES per-tile partials
// ---------------------------------------------------------------------------
__global__ void k_fin(const float* __restrict__ gna) {
    int b = blockIdx.x, d = threadIdx.x;
    float s = 0.f, q = 0.f;
#pragma unroll
    for (int tile = 0; tile < NTILES; tile++) {
        float2 v = g_part[((size_t)b * NTILES + tile) * ND + d];
        s += v.x; q += v.y;
    }
    float mean = s * (1.f / NN);
    float eh2 = q * (1.f / NN);
    float a = gna[d];
    float var = eh2 - (2.f * a - a * a) * mean * mean;
    g_mean[b * ND + d] = mean;
    g_rstd[b * ND + d] = rsqrtf(var + 1e-5f);
}

// ---------------------------------------------------------------------------
// Kernel 6: normalize in place (only needed after the final layer)
// ---------------------------------------------------------------------------
__global__ void k_norm(float* __restrict__ h, const float* __restrict__ gnw,
                       const float* __restrict__ gnb, const float* __restrict__ gna) {
    int idx = blockIdx.x * 256 + threadIdx.x;
    int d = idx & (ND - 1);
    int b = idx >> 18;
    float m = g_mean[b * ND + d];
    float rs = g_rstd[b * ND + d];
    float v = h[idx];
    h[idx] = gnw[d] * (v - gna[d] * m) * rs + gnb[d];
}

// ---------------------------------------------------------------------------
extern "C" void kernel_launch(void* const* d_in, const int* in_sizes, int n_in,
                              void* d_out, int out_size) {
    const float* inst = (const float*)d_in[0];
    const float* Wn   = (const float*)d_in[1];
    const float* bn   = (const float*)d_in[2];
    const float* Wg   = (const float*)d_in[3];
    const float* bg   = (const float*)d_in[4];
    const float* gnw  = (const float*)d_in[5];
    const float* gnb  = (const float*)d_in[6];
    const float* gna  = (const float*)d_in[7];
    float* h = (float*)d_out;

    const int SMEM_GEMM = 3 * 40960;             // 3 stages x (A 20KB + B 20KB)
    const int SMEM_Z    = 2 * 128 * (int)ZROWB;  // 72 KB
    static int smem_set = 0;
    if (!smem_set) {
        cudaFuncSetAttribute(k_gemm_mma, cudaFuncAttributeMaxDynamicSharedMemorySize, SMEM_GEMM);
        cudaFuncSetAttribute(k_z, cudaFuncAttributeMaxDynamicSharedMemorySize, SMEM_Z);
        smem_set = 1;
    }

    k_dist<<<dim3(NN, NB), 256>>>(inst);
    k_proj<<<(NB * NN * ND) / 256, 256>>>(inst, Wn, bn, h);
    for (int l = 0; l < 3; l++) {
        // layers 1,2: fuse previous layer's GraphNorm into k_z's staging pass
        k_z<<<NB * NN / 128, 256, SMEM_Z>>>(h, Wg + l * ND * ND,
                                            l > 0 ? 1 : 0, gnw, gnb, gna);
        k_gemm_mma<<<dim3(NTILES, NB), 512, SMEM_GEMM>>>(h, bg + l * ND);
        k_fin<<<NB, ND>>>(gna);
    }
    k_norm<<<(NB * NN * ND) / 256, 256>>>(h, gnw, gnb, gna);
}